// round 15
// baseline (speedup 1.0000x reference)
#include <cuda_runtime.h>

// ContrastivePredictionLoss — two-kernel, R15: granularity sweep point 4.
// Measured stage-A curve: 1024->34.7, 2048->31.0, 4096->29.8us. This round:
// 8192 blocks (128/batch, 2 float4-triples/thread). Partials now interleaved
// float2 {err,unc}: one STG.64 per block, finalize fetches 4 independent
// LDG.128/thread (one latency round) with 1024 threads.

#define NB 64
#define ELEMS_PER_BATCH (4 * 256 * 256)      // 262144
#define BLOCKS_PER_BATCH 128
#define NBLOCKS (NB * BLOCKS_PER_BATCH)      // 8192
#define THREADS_A 256
#define ELEMS_PER_BLOCK (ELEMS_PER_BATCH / BLOCKS_PER_BATCH)   // 2048
#define VECS_PER_BLOCK (ELEMS_PER_BLOCK / 4)                   // 512 float4
#define VECS_PER_THREAD (VECS_PER_BLOCK / THREADS_A)           // 2

// Scratch (allocation-free __device__ global). x = err partial, y = unc partial.
__device__ float2 g_part[NBLOCKS];

__global__ __launch_bounds__(THREADS_A)
void cpl_reduce_kernel(const float4* __restrict__ pm,
                       const float4* __restrict__ ps,
                       const float4* __restrict__ tg) {
    const int blk = blockIdx.x;                      // b * 128 + chunk
    const int tid = threadIdx.x;
    const long base = (long)blk * VECS_PER_BLOCK + tid;

    // 2 float4-triples per thread, all 6 loads independent (front-batched).
    float4 m0 = pm[base];
    float4 t0 = tg[base];
    float4 s0 = ps[base];
    float4 m1 = pm[base + THREADS_A];
    float4 t1 = tg[base + THREADS_A];
    float4 s1 = ps[base + THREADS_A];

    float se = fabsf(m0.x - t0.x) + fabsf(m0.y - t0.y)
             + fabsf(m0.z - t0.z) + fabsf(m0.w - t0.w)
             + fabsf(m1.x - t1.x) + fabsf(m1.y - t1.y)
             + fabsf(m1.z - t1.z) + fabsf(m1.w - t1.w);
    float su = (s0.x + s0.y) + (s0.z + s0.w)
             + (s1.x + s1.y) + (s1.z + s1.w);

    // Warp reduce (deterministic shuffle tree)
    #pragma unroll
    for (int off = 16; off > 0; off >>= 1) {
        se += __shfl_down_sync(0xFFFFFFFFu, se, off);
        su += __shfl_down_sync(0xFFFFFFFFu, su, off);
    }

    __shared__ float s_se[THREADS_A / 32];
    __shared__ float s_su[THREADS_A / 32];
    const int wid = tid >> 5;
    const int lid = tid & 31;
    if (lid == 0) { s_se[wid] = se; s_su[wid] = su; }
    __syncthreads();

    if (wid == 0) {
        se = (lid < THREADS_A / 32) ? s_se[lid] : 0.0f;
        su = (lid < THREADS_A / 32) ? s_su[lid] : 0.0f;
        #pragma unroll
        for (int off = 4; off > 0; off >>= 1) {
            se += __shfl_down_sync(0xFFFFFFFFu, se, off);
            su += __shfl_down_sync(0xFFFFFFFFu, su, off);
        }
        if (lid == 0) {
            g_part[blk] = make_float2(se, su);
        }
    }
}

#define THREADS_B 1024

__global__ __launch_bounds__(THREADS_B)
void cpl_finalize_kernel(float* __restrict__ out) {
    const int tid = threadIdx.x;
    const int wid = tid >> 5;
    const int lid = tid & 31;

    // 8192 float2 partials = 4096 float4; batch b owns float4 [b*64, b*64+64).
    // Thread (b = tid>>4, q = tid&15): 4 independent float4 loads — all 4096
    // loads issue in a single latency round across the block.
    const int b = tid >> 4;
    const int q = tid & 15;
    const float4* p4 = (const float4*)g_part;

    float pe = 0.0f, pu = 0.0f;
    #pragma unroll
    for (int k = 0; k < 4; k++) {
        float4 v = p4[b * 64 + q * 4 + k];   // {err,unc,err,unc}
        pe += v.x + v.z;
        pu += v.y + v.w;
    }

    // Reduce across the 16 lanes that share a batch (contiguous within a warp).
    #pragma unroll
    for (int off = 8; off > 0; off >>= 1) {
        pe += __shfl_down_sync(0xFFFFFFFFu, pe, off);
        pu += __shfl_down_sync(0xFFFFFFFFu, pu, off);
    }

    __shared__ float errs[NB];
    __shared__ float uncs[NB];
    if (q == 0) {
        const float inv = 1.0f / (float)ELEMS_PER_BATCH;
        errs[b] = pe * inv;
        uncs[b] = pu * inv;
    }
    __syncthreads();

    // Pairwise hinge over upper triangle (i < j), fixed iteration order.
    float acc = 0.0f;
    #pragma unroll
    for (int p = tid; p < NB * NB; p += THREADS_B) {
        const int i = p >> 6;
        const int j = p & 63;
        if (i < j) {
            const float d = ((errs[i] > errs[j]) ? (uncs[j] - uncs[i])
                                                 : (uncs[i] - uncs[j])) + 1.0f;
            acc += fmaxf(d, 0.0f);
        }
    }

    #pragma unroll
    for (int off = 16; off > 0; off >>= 1)
        acc += __shfl_down_sync(0xFFFFFFFFu, acc, off);

    __shared__ float s_acc[THREADS_B / 32];
    if (lid == 0) s_acc[wid] = acc;
    __syncthreads();

    if (tid == 0) {
        float total = 0.0f;
        #pragma unroll
        for (int w = 0; w < THREADS_B / 32; w++) total += s_acc[w];
        const int num_pairs = NB * (NB - 1) / 2;   // 2016
        out[0] = total / (float)num_pairs;
    }
}

extern "C" void kernel_launch(void* const* d_in, const int* in_sizes, int n_in,
                              void* d_out, int out_size) {
    const float4* pm = (const float4*)d_in[0];   // pred_mean
    const float4* ps = (const float4*)d_in[1];   // pred_std
    const float4* tg = (const float4*)d_in[2];   // targets
    float* out = (float*)d_out;

    cpl_reduce_kernel<<<NBLOCKS, THREADS_A>>>(pm, ps, tg);
    cpl_finalize_kernel<<<1, THREADS_B>>>(out);
}

// round 17
// speedup vs baseline: 1.0009x; 1.0009x over previous
#include <cuda_runtime.h>

// ContrastivePredictionLoss — two-kernel, R17 (verbatim retry of R16 after
// broker/container infra failure — same flake pattern as R2/R7/R9/R11, all of
// which passed unchanged on resubmission).
//
// Stage A: best-measured grid (4096 blocks, 4 vec/thread, 2-deep pipeline).
//          Per-block partials go through atomicAdd(u64) in Q34.30 fixed point
//          into 64 per-batch accumulators — integer adds are exactly
//          associative => bitwise deterministic for any arrival order.
//          128 cold addresses, ~64 ops each over 30us: no contention, and no
//          single-hot-address handshake (that's what sank the fused R3).
// Stage B: finalize reads just 128 u64 (one latency round), converts, hinges.
//          Resets accumulators after reading so each graph replay starts at 0.

#define NB 64
#define ELEMS_PER_BATCH (4 * 256 * 256)      // 262144
#define BLOCKS_PER_BATCH 64
#define NBLOCKS (NB * BLOCKS_PER_BATCH)      // 4096
#define THREADS_A 256
#define ELEMS_PER_BLOCK (ELEMS_PER_BATCH / BLOCKS_PER_BATCH)   // 4096
#define VECS_PER_BLOCK (ELEMS_PER_BLOCK / 4)                   // 1024 float4
#define VECS_PER_THREAD (VECS_PER_BLOCK / THREADS_A)           // 4

#define FP_SCALE 1073741824.0   // 2^30

// Accumulators (allocation-free __device__ globals; zero-initialized at load,
// reset by the finalize kernel after each read).
__device__ unsigned long long g_acc_err[NB];
__device__ unsigned long long g_acc_unc[NB];

__global__ __launch_bounds__(THREADS_A)
void cpl_reduce_kernel(const float4* __restrict__ pm,
                       const float4* __restrict__ ps,
                       const float4* __restrict__ tg) {
    const int blk = blockIdx.x;                      // b * 64 + chunk
    const int tid = threadIdx.x;
    const long base = (long)blk * VECS_PER_BLOCK + tid;

    float se = 0.0f;   // sum |pm - tg|
    float su = 0.0f;   // sum ps

    // 2-deep software pipeline.
    float4 m0 = pm[base];
    float4 t0 = tg[base];
    float4 s0 = ps[base];

    #pragma unroll
    for (int i = 1; i < VECS_PER_THREAD; i++) {
        const long idx = base + (long)i * THREADS_A;
        float4 m1 = pm[idx];
        float4 t1 = tg[idx];
        float4 s1 = ps[idx];

        se += fabsf(m0.x - t0.x) + fabsf(m0.y - t0.y)
            + fabsf(m0.z - t0.z) + fabsf(m0.w - t0.w);
        su += s0.x + s0.y + s0.z + s0.w;

        m0 = m1; t0 = t1; s0 = s1;
    }
    se += fabsf(m0.x - t0.x) + fabsf(m0.y - t0.y)
        + fabsf(m0.z - t0.z) + fabsf(m0.w - t0.w);
    su += s0.x + s0.y + s0.z + s0.w;

    // Warp reduce (deterministic shuffle tree)
    #pragma unroll
    for (int off = 16; off > 0; off >>= 1) {
        se += __shfl_down_sync(0xFFFFFFFFu, se, off);
        su += __shfl_down_sync(0xFFFFFFFFu, su, off);
    }

    __shared__ float s_se[THREADS_A / 32];
    __shared__ float s_su[THREADS_A / 32];
    const int wid = tid >> 5;
    const int lid = tid & 31;
    if (lid == 0) { s_se[wid] = se; s_su[wid] = su; }
    __syncthreads();

    if (wid == 0) {
        se = (lid < THREADS_A / 32) ? s_se[lid] : 0.0f;
        su = (lid < THREADS_A / 32) ? s_su[lid] : 0.0f;
        #pragma unroll
        for (int off = 4; off > 0; off >>= 1) {
            se += __shfl_down_sync(0xFFFFFFFFu, se, off);
            su += __shfl_down_sync(0xFFFFFFFFu, su, off);
        }
        if (lid == 0) {
            // Q34.30 fixed point: exact integer accumulation, order-invariant.
            const int b = blk >> 6;   // blk / BLOCKS_PER_BATCH
            unsigned long long fe =
                (unsigned long long)__double2ll_rn((double)se * FP_SCALE);
            unsigned long long fu =
                (unsigned long long)__double2ll_rn((double)su * FP_SCALE);
            atomicAdd(&g_acc_err[b], fe);   // REDG: no return value used
            atomicAdd(&g_acc_unc[b], fu);
        }
    }
}

#define THREADS_B 1024

__global__ __launch_bounds__(THREADS_B)
void cpl_finalize_kernel(float* __restrict__ out) {
    const int tid = threadIdx.x;
    const int wid = tid >> 5;
    const int lid = tid & 31;

    __shared__ float errs[NB];
    __shared__ float uncs[NB];

    // Threads 0..63: fetch both accumulators (2 independent LDG.64, one
    // latency round for the whole fetch), convert, and reset for next replay.
    if (tid < NB) {
        unsigned long long ae = g_acc_err[tid];
        unsigned long long au = g_acc_unc[tid];
        g_acc_err[tid] = 0ull;
        g_acc_unc[tid] = 0ull;
        const double inv = 1.0 / (FP_SCALE * (double)ELEMS_PER_BATCH);
        errs[tid] = (float)(__ull2double_rn(ae) * inv);
        uncs[tid] = (float)(__ull2double_rn(au) * inv);
    }
    __syncthreads();

    // Pairwise hinge over upper triangle (i < j), fixed iteration order.
    float acc = 0.0f;
    #pragma unroll
    for (int p = tid; p < NB * NB; p += THREADS_B) {
        const int i = p >> 6;
        const int j = p & 63;
        if (i < j) {
            const float d = ((errs[i] > errs[j]) ? (uncs[j] - uncs[i])
                                                 : (uncs[i] - uncs[j])) + 1.0f;
            acc += fmaxf(d, 0.0f);
        }
    }

    #pragma unroll
    for (int off = 16; off > 0; off >>= 1)
        acc += __shfl_down_sync(0xFFFFFFFFu, acc, off);

    __shared__ float s_acc[THREADS_B / 32];
    if (lid == 0) s_acc[wid] = acc;
    __syncthreads();

    if (tid == 0) {
        float total = 0.0f;
        #pragma unroll
        for (int w = 0; w < THREADS_B / 32; w++) total += s_acc[w];
        const int num_pairs = NB * (NB - 1) / 2;   // 2016
        out[0] = total / (float)num_pairs;
    }
}

extern "C" void kernel_launch(void* const* d_in, const int* in_sizes, int n_in,
                              void* d_out, int out_size) {
    const float4* pm = (const float4*)d_in[0];   // pred_mean
    const float4* ps = (const float4*)d_in[1];   // pred_std
    const float4* tg = (const float4*)d_in[2];   // targets
    float* out = (float*)d_out;

    cpl_reduce_kernel<<<NBLOCKS, THREADS_A>>>(pm, ps, tg);
    cpl_finalize_kernel<<<1, THREADS_B>>>(out);
}